// round 2
// baseline (speedup 1.0000x reference)
#include <cuda_runtime.h>

// Modulated deformable conv 3x3, in_ch=out_ch=1, stride=1, pad=1, dil=1.
// depth  [B,1,H,W], mask [B,9,H,W], offset [B,9,2,H,W] (dy,dx per tap),
// w [1,1,3,3], b [1]. Output [B,1,H,W]. H=W=512 hardcoded.

#define Hc 512
#define Wc 512
#define HWc (Hc * Wc)

__device__ __forceinline__ float bilin_sample(const float* __restrict__ img,
                                              float y, float x) {
    float y0f = floorf(y);
    float x0f = floorf(x);
    float wy = y - y0f;
    float wx = x - x0f;
    int y0 = (int)y0f;
    int x0 = (int)x0f;
    int base = (y0 << 9) + x0;   // W = 512
    bool vy0 = (unsigned)y0 < (unsigned)Hc;
    bool vy1 = (unsigned)(y0 + 1) < (unsigned)Hc;
    bool vx0 = (unsigned)x0 < (unsigned)Wc;
    bool vx1 = (unsigned)(x0 + 1) < (unsigned)Wc;
    float v00 = (vy0 && vx0) ? __ldg(img + base)          : 0.0f;
    float v01 = (vy0 && vx1) ? __ldg(img + base + 1)      : 0.0f;
    float v10 = (vy1 && vx0) ? __ldg(img + base + Wc)     : 0.0f;
    float v11 = (vy1 && vx1) ? __ldg(img + base + Wc + 1) : 0.0f;
    float top = fmaf(wx, v01 - v00, v00);
    float bot = fmaf(wx, v11 - v10, v10);
    return fmaf(wy, bot - top, top);
}

__global__ __launch_bounds__(256, 6)
void dcn_kernel(const float* __restrict__ depth,
                const float* __restrict__ mask,
                const float* __restrict__ off,
                const float* __restrict__ w9,
                const float* __restrict__ bias,
                float* __restrict__ out,
                int B)
{
    int tid = blockIdx.x * blockDim.x + threadIdx.x;
    int total4 = B * (HWc / 4);
    if (tid >= total4) return;

    int b   = tid / (HWc / 4);
    int pix = (tid - b * (HWc / 4)) * 4;   // 4 consecutive x-pixels
    int iy  = pix >> 9;                    // pix / 512
    int ix  = pix & 511;                   // pix % 512

    const float* img  = depth + (size_t)b * HWc;
    const float* mptr = mask  + (size_t)b * 9  * HWc + pix;
    const float* optr = off   + (size_t)b * 18 * HWc + pix;

    // Hoist conv weights (9 floats, uniform across threads -> const-cache)
    float wreg[9];
    #pragma unroll
    for (int t = 0; t < 9; t++) wreg[t] = __ldg(w9 + t);

    float acc0 = 0.0f, acc1 = 0.0f, acc2 = 0.0f, acc3 = 0.0f;

    #pragma unroll 3
    for (int t = 0; t < 9; t++) {
        // offset layout: (b, tap, {dy,dx}, H, W). Streaming, read-once -> .cs
        float4 dy4 = __ldcs((const float4*)(optr + (size_t)(2 * t)     * HWc));
        float4 dx4 = __ldcs((const float4*)(optr + (size_t)(2 * t + 1) * HWc));
        float4 m4  = __ldcs((const float4*)(mptr + (size_t)t           * HWc));
        float  wt  = wreg[t];

        float ybase = (float)(iy - 1 + t / 3);
        float xbase = (float)(ix - 1 + t % 3);

        float s;
        s = bilin_sample(img, ybase + dy4.x, xbase + 0.0f + dx4.x);
        acc0 = fmaf(s, m4.x * wt, acc0);
        s = bilin_sample(img, ybase + dy4.y, xbase + 1.0f + dx4.y);
        acc1 = fmaf(s, m4.y * wt, acc1);
        s = bilin_sample(img, ybase + dy4.z, xbase + 2.0f + dx4.z);
        acc2 = fmaf(s, m4.z * wt, acc2);
        s = bilin_sample(img, ybase + dy4.w, xbase + 3.0f + dx4.w);
        acc3 = fmaf(s, m4.w * wt, acc3);
    }

    float bv = __ldg(bias);
    float4 o;
    o.x = acc0 + bv;
    o.y = acc1 + bv;
    o.z = acc2 + bv;
    o.w = acc3 + bv;
    *(float4*)(out + (size_t)b * HWc + pix) = o;
}

extern "C" void kernel_launch(void* const* d_in, const int* in_sizes, int n_in,
                              void* d_out, int out_size)
{
    const float* depth = (const float*)d_in[0];
    const float* mask  = (const float*)d_in[1];
    const float* off   = (const float*)d_in[2];
    const float* w9    = (const float*)d_in[3];
    const float* bias  = (const float*)d_in[4];
    float* out = (float*)d_out;

    int B = in_sizes[0] / HWc;
    int total4 = B * (HWc / 4);
    int threads = 256;
    int blocks = (total4 + threads - 1) / threads;
    dcn_kernel<<<blocks, threads>>>(depth, mask, off, w9, bias, out, B);
}

// round 3
// speedup vs baseline: 1.1620x; 1.1620x over previous
#include <cuda_runtime.h>

// Modulated deformable conv 3x3, in_ch=out_ch=1, stride=1, pad=1, dil=1.
// depth  [B,1,H,W], mask [B,9,H,W], offset [B,9,2,H,W] (dy,dx per tap),
// w [1,1,3,3], b [1]. Output [B,1,H,W]. H=W=512 hardcoded.
//
// R3: software-pipelined tap loop (prefetch distance 1 on streaming operands),
// full unroll, __ldg everywhere, reg cap 64 (4 blocks/SM @ 256 thr).

#define Hc 512
#define Wc 512
#define HWc (Hc * Wc)

__device__ __forceinline__ float bilin_sample(const float* __restrict__ img,
                                              float y, float x) {
    float y0f = floorf(y);
    float x0f = floorf(x);
    float wy = y - y0f;
    float wx = x - x0f;
    int y0 = (int)y0f;
    int x0 = (int)x0f;
    int base = (y0 << 9) + x0;   // W = 512
    bool vy0 = (unsigned)y0 < (unsigned)Hc;
    bool vy1 = (unsigned)(y0 + 1) < (unsigned)Hc;
    bool vx0 = (unsigned)x0 < (unsigned)Wc;
    bool vx1 = (unsigned)(x0 + 1) < (unsigned)Wc;
    float v00 = (vy0 && vx0) ? __ldg(img + base)          : 0.0f;
    float v01 = (vy0 && vx1) ? __ldg(img + base + 1)      : 0.0f;
    float v10 = (vy1 && vx0) ? __ldg(img + base + Wc)     : 0.0f;
    float v11 = (vy1 && vx1) ? __ldg(img + base + Wc + 1) : 0.0f;
    float top = fmaf(wx, v01 - v00, v00);
    float bot = fmaf(wx, v11 - v10, v10);
    return fmaf(wy, bot - top, top);
}

__global__ __launch_bounds__(256, 4)
void dcn_kernel(const float* __restrict__ depth,
                const float* __restrict__ mask,
                const float* __restrict__ off,
                const float* __restrict__ w9,
                const float* __restrict__ bias,
                float* __restrict__ out,
                int B)
{
    int tid = blockIdx.x * blockDim.x + threadIdx.x;
    int total4 = B * (HWc / 4);
    if (tid >= total4) return;

    int b   = tid / (HWc / 4);
    int pix = (tid - b * (HWc / 4)) * 4;   // 4 consecutive x-pixels
    int iy  = pix >> 9;                    // pix / 512
    int ix  = pix & 511;                   // pix % 512

    const float* img  = depth + (size_t)b * HWc;
    const float* mptr = mask  + (size_t)b * 9  * HWc + pix;
    const float* optr = off   + (size_t)b * 18 * HWc + pix;

    float acc0 = 0.0f, acc1 = 0.0f, acc2 = 0.0f, acc3 = 0.0f;

    // Prologue: tap 0 streaming operands
    float4 dy4 = __ldg((const float4*)(optr));
    float4 dx4 = __ldg((const float4*)(optr + (size_t)HWc));
    float4 m4  = __ldg((const float4*)(mptr));

    #pragma unroll
    for (int t = 0; t < 9; t++) {
        // Prefetch tap t+1 streaming operands (overlaps gather latency below)
        float4 ndy, ndx, nm;
        if (t < 8) {
            ndy = __ldg((const float4*)(optr + (size_t)(2 * t + 2) * HWc));
            ndx = __ldg((const float4*)(optr + (size_t)(2 * t + 3) * HWc));
            nm  = __ldg((const float4*)(mptr + (size_t)(t + 1)     * HWc));
        }

        float wt = __ldg(w9 + t);
        float ybase = (float)(iy - 1 + t / 3);
        float xbase = (float)(ix - 1 + t % 3);

        float s;
        s = bilin_sample(img, ybase + dy4.x, xbase + 0.0f + dx4.x);
        acc0 = fmaf(s, m4.x * wt, acc0);
        s = bilin_sample(img, ybase + dy4.y, xbase + 1.0f + dx4.y);
        acc1 = fmaf(s, m4.y * wt, acc1);
        s = bilin_sample(img, ybase + dy4.z, xbase + 2.0f + dx4.z);
        acc2 = fmaf(s, m4.z * wt, acc2);
        s = bilin_sample(img, ybase + dy4.w, xbase + 3.0f + dx4.w);
        acc3 = fmaf(s, m4.w * wt, acc3);

        if (t < 8) { dy4 = ndy; dx4 = ndx; m4 = nm; }
    }

    float bv = __ldg(bias);
    float4 o;
    o.x = acc0 + bv;
    o.y = acc1 + bv;
    o.z = acc2 + bv;
    o.w = acc3 + bv;
    *(float4*)(out + (size_t)b * HWc + pix) = o;
}

extern "C" void kernel_launch(void* const* d_in, const int* in_sizes, int n_in,
                              void* d_out, int out_size)
{
    const float* depth = (const float*)d_in[0];
    const float* mask  = (const float*)d_in[1];
    const float* off   = (const float*)d_in[2];
    const float* w9    = (const float*)d_in[3];
    const float* bias  = (const float*)d_in[4];
    float* out = (float*)d_out;

    int B = in_sizes[0] / HWc;
    int total4 = B * (HWc / 4);
    int threads = 256;
    int blocks = (total4 + threads - 1) / threads;
    dcn_kernel<<<blocks, threads>>>(depth, mask, off, w9, bias, out, B);
}